// round 17
// baseline (speedup 1.0000x reference)
#include <cuda_runtime.h>

// Row-normalize: out[b,i,j] = adj[b,i,j] / sum_j adj[b,i,j]  (nan/inf inv -> 0)
// Two tensors of [16, 1024, 1024] fp32; output = concat(out0, out1).
//
// Persistent grid, warp-per-row, grid-stride loop with CROSS-ITERATION
// PREFETCH: the next row's 8 LDG.128 are issued before the current row's
// reduce/scale/store, so the DRAM read queue stays non-empty through every
// store burst, and there are no CTA wave transitions at all.

constexpr int N       = 1024;    // row length
constexpr int THREADS = 256;     // 8 warps per CTA
constexpr int WARPS   = THREADS / 32;
constexpr int VPT     = 8;       // float4 per thread (32*8*4 = 1024)
constexpr int GRID    = 152 * 8; // persistent: 8 CTAs per SM on 152 SMs

__device__ __forceinline__ void load_row(const float* __restrict__ in0,
                                         const float* __restrict__ in1,
                                         long long row, int rows_per_tensor,
                                         int lane, float4 (&v)[VPT])
{
    const bool second = row >= rows_per_tensor;
    const float* __restrict__ src = second ? in1 : in0;
    const long long local_row = second ? (row - rows_per_tensor) : row;
    const float4* __restrict__ s =
        reinterpret_cast<const float4*>(src) + local_row * (N / 4) + lane;
    #pragma unroll
    for (int i = 0; i < VPT; ++i)
        v[i] = __ldcs(s + i * 32);
}

__device__ __forceinline__ void reduce_scale_store(float4 (&v)[VPT],
                                                   float* __restrict__ out,
                                                   long long row, int lane)
{
    float p = 0.0f;
    #pragma unroll
    for (int i = 0; i < VPT; ++i)
        p += ((v[i].x + v[i].y) + (v[i].z + v[i].w));
    #pragma unroll
    for (int off = 16; off > 0; off >>= 1)
        p += __shfl_xor_sync(0xFFFFFFFFu, p, off);

    float inv = 1.0f / p;
    if (!isfinite(inv)) inv = 0.0f;

    float4* __restrict__ d =
        reinterpret_cast<float4*>(out) + row * (N / 4) + lane;
    #pragma unroll
    for (int i = 0; i < VPT; ++i) {
        v[i].x *= inv; v[i].y *= inv; v[i].z *= inv; v[i].w *= inv;
        __stcs(d + i * 32, v[i]);
    }
}

__global__ __launch_bounds__(THREADS)
void row_norm_kernel(const float* __restrict__ in0,
                     const float* __restrict__ in1,
                     float* __restrict__ out,
                     int rows_per_tensor)   // 16384
{
    const int lane = threadIdx.x & 31;
    const int wid  = threadIdx.x >> 5;

    const long long total_rows  = 2LL * rows_per_tensor;       // 32768
    const long long total_warps = (long long)gridDim.x * WARPS; // 9728
    long long row = (long long)blockIdx.x * WARPS + wid;

    if (row >= total_rows) return;

    float4 cur[VPT];
    load_row(in0, in1, row, rows_per_tensor, lane, cur);

    while (true) {
        const long long next = row + total_warps;
        if (next < total_rows) {
            float4 nxt[VPT];
            // Prefetch: next row's loads go out BEFORE we wait on cur[].
            load_row(in0, in1, next, rows_per_tensor, lane, nxt);
            reduce_scale_store(cur, out, row, lane);
            #pragma unroll
            for (int i = 0; i < VPT; ++i) cur[i] = nxt[i];
            row = next;
        } else {
            reduce_scale_store(cur, out, row, lane);
            break;
        }
    }
}

extern "C" void kernel_launch(void* const* d_in, const int* in_sizes, int n_in,
                              void* d_out, int out_size)
{
    const float* adj0 = (const float*)d_in[0];
    const float* adj1 = (const float*)d_in[1];
    float* out = (float*)d_out;

    const int rows_per_tensor = in_sizes[0] / N;   // 16384

    row_norm_kernel<<<GRID, THREADS>>>(adj0, adj1, out, rows_per_tensor);
}